// round 1
// baseline (speedup 1.0000x reference)
#include <cuda_runtime.h>
#include <math.h>

#define BB 2
#define TT 2048
#define CC 1024
#define HQ 16
#define HKV 2
#define HD 64
#define MROWS (BB*TT)   // 4096

// Scratch (device globals: allocation APIs are forbidden)
__device__ float g_q[BB*TT*HQ*HD];    // [b][t][h][d]  16 MB
__device__ float g_k[BB*TT*HKV*HD];   // [b][t][h][d]   2 MB
__device__ float g_v[BB*TT*HKV*HD];   //                2 MB
__device__ float g_y[BB*TT*HQ*HD];    // attention out 16 MB

// ---------------------------------------------------------------------------
// SGEMM: out[m][n] = sum_k X[m][k] * W[n][k] + bias[n]
// BM=BN=64, BK=16, 256 threads, 4x4 register tile.
// smem stored k-major (transposed) so compute reads are float4 + conflict-free.
// Requires M%64==0, N%64==0, K%16==0 (true for all calls here).
// ---------------------------------------------------------------------------
__global__ __launch_bounds__(256) void sgemm_bias(
    const float* __restrict__ X, const float* __restrict__ W,
    const float* __restrict__ bias, float* __restrict__ out,
    int M, int N, int K)
{
    __shared__ float As[16][68];
    __shared__ float Ws[16][68];
    const int tid = threadIdx.x;
    const int ty = tid >> 4, tx = tid & 15;
    const int m0 = blockIdx.y * 64, n0 = blockIdx.x * 64;
    const int r = tid >> 2, kc = (tid & 3) << 2;

    float acc[4][4] = {};

    for (int k0 = 0; k0 < K; k0 += 16) {
        __syncthreads();
        float4 a = *(const float4*)(X + (size_t)(m0 + r) * K + k0 + kc);
        As[kc+0][r] = a.x; As[kc+1][r] = a.y; As[kc+2][r] = a.z; As[kc+3][r] = a.w;
        float4 w = *(const float4*)(W + (size_t)(n0 + r) * K + k0 + kc);
        Ws[kc+0][r] = w.x; Ws[kc+1][r] = w.y; Ws[kc+2][r] = w.z; Ws[kc+3][r] = w.w;
        __syncthreads();
        #pragma unroll
        for (int k = 0; k < 16; ++k) {
            float4 av = *(const float4*)&As[k][ty << 2];
            float4 wv = *(const float4*)&Ws[k][tx << 2];
            float am[4] = {av.x, av.y, av.z, av.w};
            float wn[4] = {wv.x, wv.y, wv.z, wv.w};
            #pragma unroll
            for (int i = 0; i < 4; ++i)
                #pragma unroll
                for (int j = 0; j < 4; ++j)
                    acc[i][j] += am[i] * wn[j];
        }
    }

    #pragma unroll
    for (int i = 0; i < 4; ++i) {
        int m = m0 + (ty << 2) + i;
        #pragma unroll
        for (int j = 0; j < 4; ++j) {
            int n = n0 + (tx << 2) + j;
            out[(size_t)m * N + n] = acc[i][j] + bias[n];
        }
    }
}

// ---------------------------------------------------------------------------
// In-place RoPE over buf laid out [b][t][H][HD].
// Pair p uses sin = rc[t][2p], cos = rc[t][2p+1]:
//   out[2p]   = x[2p]*cos - x[2p+1]*sin
//   out[2p+1] = x[2p+1]*cos + x[2p]*sin
// postscale folds q's scale^2 = 1/HD (applied twice in reference).
// ---------------------------------------------------------------------------
__global__ void rope_kernel(float* __restrict__ buf,
                            const float* __restrict__ rc,
                            int H, float postscale, int npairs)
{
    int idx = blockIdx.x * blockDim.x + threadIdx.x;
    if (idx >= npairs) return;
    int pair = idx & 31;                  // HD/2 = 32 pairs
    int t = (idx / (32 * H)) % TT;
    float2 xv = *(float2*)(buf + 2 * (size_t)idx);
    float sn = rc[t * HD + 2 * pair];
    float cs = rc[t * HD + 2 * pair + 1];
    float2 ov;
    ov.x = (xv.x * cs - xv.y * sn) * postscale;
    ov.y = (xv.y * cs + xv.x * sn) * postscale;
    *(float2*)(buf + 2 * (size_t)idx) = ov;
}

// ---------------------------------------------------------------------------
// Flash attention, fp32. grid (T/64, HQ, B), 256 threads (8 warps).
// Block handles 64 q rows for one (b,h). Warp w owns rows 8w..8w+7.
// Lane l owns k-column l of each 32-wide K tile -> softmax = warp shuffles.
// O accumulators: lane holds O[i][l] and O[i][l+32] for the 8 rows.
// ---------------------------------------------------------------------------
__global__ __launch_bounds__(256) void flash_kernel(
    const float* __restrict__ q, const float* __restrict__ k,
    const float* __restrict__ v, float* __restrict__ y)
{
    __shared__ float Qs[64][68];
    __shared__ float Ks[32][68];
    __shared__ float Vs[32][68];
    __shared__ float Ps[64][36];

    const int qb = blockIdx.x, h = blockIdx.y, b = blockIdx.z;
    const int qs = qb * 64;
    const int hk = h / (HQ / HKV);
    const int tid = threadIdx.x, w = tid >> 5, l = tid & 31;

    // Load Q tile (64 x 64)
    for (int it = tid; it < 64 * 16; it += 256) {
        int rr = it >> 4, c4 = it & 15;
        float4 val = *(const float4*)(q +
            ((((size_t)b * TT + qs + rr) * HQ + h) * HD) + c4 * 4);
        *(float4*)&Qs[rr][c4 * 4] = val;
    }

    float m_[8], lsum[8], O0[8], O1[8];
    #pragma unroll
    for (int i = 0; i < 8; ++i) { m_[i] = -1e30f; lsum[i] = 0.f; O0[i] = 0.f; O1[i] = 0.f; }

    const int ktmax = qs / 32 + 1;   // inclusive; causal early exit
    for (int kt = 0; kt <= ktmax; ++kt) {
        __syncthreads();
        // Load K,V tiles (32 x 64 each)
        for (int it = tid; it < 32 * 16; it += 256) {
            int rr = it >> 4, c4 = it & 15;
            size_t base = ((((size_t)b * TT + kt * 32 + rr) * HKV + hk) * HD) + c4 * 4;
            *(float4*)&Ks[rr][c4 * 4] = *(const float4*)(k + base);
            *(float4*)&Vs[rr][c4 * 4] = *(const float4*)(v + base);
        }
        __syncthreads();

        // S = Q . K^T  (lane l = k-column, 8 rows per warp)
        float s[8] = {0.f,0.f,0.f,0.f,0.f,0.f,0.f,0.f};
        #pragma unroll
        for (int d4 = 0; d4 < 16; ++d4) {
            float4 kv = *(const float4*)&Ks[l][d4 * 4];
            #pragma unroll
            for (int i = 0; i < 8; ++i) {
                float4 qv = *(const float4*)&Qs[8 * w + i][d4 * 4];
                s[i] += qv.x * kv.x + qv.y * kv.y + qv.z * kv.z + qv.w * kv.w;
            }
        }

        // Online softmax (per row, warp-wide)
        const int gcol = kt * 32 + l;
        #pragma unroll
        for (int i = 0; i < 8; ++i) {
            int grow = qs + 8 * w + i;
            float sv = (gcol <= grow) ? s[i] : -1e30f;
            float mx = sv;
            #pragma unroll
            for (int off = 16; off; off >>= 1)
                mx = fmaxf(mx, __shfl_xor_sync(0xffffffffu, mx, off));
            float newm = fmaxf(m_[i], mx);
            float p = __expf(sv - newm);
            float rs = p;
            #pragma unroll
            for (int off = 16; off; off >>= 1)
                rs += __shfl_xor_sync(0xffffffffu, rs, off);
            float corr = __expf(m_[i] - newm);
            lsum[i] = lsum[i] * corr + rs;
            O0[i] *= corr; O1[i] *= corr;
            m_[i] = newm;
            Ps[8 * w + i][l] = p;
        }
        __syncwarp();

        // O += P . V  (rows owned by this warp; d split across lanes)
        #pragma unroll
        for (int j4 = 0; j4 < 8; ++j4) {
            float4 p4[8];
            #pragma unroll
            for (int i = 0; i < 8; ++i)
                p4[i] = *(const float4*)&Ps[8 * w + i][j4 * 4];
            #pragma unroll
            for (int jj = 0; jj < 4; ++jj) {
                int j = j4 * 4 + jj;
                float v0 = Vs[j][l], v1 = Vs[j][l + 32];
                #pragma unroll
                for (int i = 0; i < 8; ++i) {
                    float pv = (jj == 0) ? p4[i].x : (jj == 1) ? p4[i].y
                             : (jj == 2) ? p4[i].z : p4[i].w;
                    O0[i] += pv * v0;
                    O1[i] += pv * v1;
                }
            }
        }
        // next iteration's __syncthreads covers the WAR hazard on Ps/Ks/Vs
    }

    // Normalize + write y in [b][t][h][d]
    #pragma unroll
    for (int i = 0; i < 8; ++i) {
        float inv = 1.f / lsum[i];
        int grow = qs + 8 * w + i;
        size_t base = (((size_t)b * TT + grow) * HQ + h) * HD;
        y[base + l]      = O0[i] * inv;
        y[base + l + 32] = O1[i] * inv;
    }
}

// ---------------------------------------------------------------------------
extern "C" void kernel_launch(void* const* d_in, const int* in_sizes, int n_in,
                              void* d_out, int out_size)
{
    const float* x  = (const float*)d_in[0];
    const float* rc = (const float*)d_in[1];
    const float* Wq = (const float*)d_in[2];
    const float* bq = (const float*)d_in[3];
    const float* Wk = (const float*)d_in[4];
    const float* bk = (const float*)d_in[5];
    const float* Wv = (const float*)d_in[6];
    const float* bv = (const float*)d_in[7];
    const float* Wo = (const float*)d_in[8];
    const float* bo = (const float*)d_in[9];
    float* out = (float*)d_out;

    float *qb, *kb, *vb, *yb;
    cudaGetSymbolAddress((void**)&qb, g_q);
    cudaGetSymbolAddress((void**)&kb, g_k);
    cudaGetSymbolAddress((void**)&vb, g_v);
    cudaGetSymbolAddress((void**)&yb, g_y);

    // QKV projections (x @ W.T + b), outputs already in [b][t][h][d] row-major
    sgemm_bias<<<dim3(CC / 64, MROWS / 64), 256>>>(x, Wq, bq, qb, MROWS, HQ * HD, CC);
    sgemm_bias<<<dim3((HKV * HD) / 64, MROWS / 64), 256>>>(x, Wk, bk, kb, MROWS, HKV * HD, CC);
    sgemm_bias<<<dim3((HKV * HD) / 64, MROWS / 64), 256>>>(x, Wv, bv, vb, MROWS, HKV * HD, CC);

    // RoPE (+ fold scale^2 = 1/HD into q)
    {
        int nq = BB * TT * HQ * (HD / 2);
        int nk = BB * TT * HKV * (HD / 2);
        rope_kernel<<<(nq + 255) / 256, 256>>>(qb, rc, HQ, 1.0f / (float)HD, nq);
        rope_kernel<<<(nk + 255) / 256, 256>>>(kb, rc, HKV, 1.0f, nk);
    }

    // Causal flash attention
    flash_kernel<<<dim3(TT / 64, HQ, BB), 256>>>(qb, kb, vb, yb);

    // Output projection
    sgemm_bias<<<dim3(CC / 64, MROWS / 64), 256>>>(yb, Wo, bo, out, MROWS, CC, CC);
}

// round 2
// speedup vs baseline: 2.2292x; 2.2292x over previous
#include <cuda_runtime.h>
#include <math.h>

#define BB 2
#define TT 2048
#define CC 1024
#define HQ 16
#define HKV 2
#define HD 64
#define MROWS (BB*TT)   // 4096

typedef unsigned long long u64;

// Scratch (device globals: allocation APIs are forbidden)
__device__ float g_q[BB*TT*HQ*HD];    // [b][t][h][d]  16 MB
__device__ float g_k[BB*TT*HKV*HD];   // [b][t][h][d]   2 MB
__device__ float g_v[BB*TT*HKV*HD];   //                2 MB
__device__ float g_y[BB*TT*HQ*HD];    // attention out 16 MB

// ---------------------------------------------------------------------------
// Packed fp32x2 helpers (Blackwell FFMA2 path)
// ---------------------------------------------------------------------------
__device__ __forceinline__ u64 pk2(float lo, float hi) {
    u64 r; asm("mov.b64 %0, {%1, %2};" : "=l"(r) : "f"(lo), "f"(hi)); return r;
}
__device__ __forceinline__ void upk2(u64 v, float& lo, float& hi) {
    asm("mov.b64 {%0, %1}, %2;" : "=f"(lo), "=f"(hi) : "l"(v));
}
__device__ __forceinline__ void ffma2(u64& d, u64 a, u64 b) {
    asm("fma.rn.f32x2 %0, %1, %2, %0;" : "+l"(d) : "l"(a), "l"(b));
}
__device__ __forceinline__ void fmul2(u64& d, u64 a) {
    asm("mul.rn.f32x2 %0, %0, %1;" : "+l"(d) : "l"(a));
}

// ---------------------------------------------------------------------------
// GEMM tile: out[m][n] = sum_k X[m][k]*W[n][k] + bias[n]
// 128x128x16, 256 threads, 8x8 micro-tile (split chunks {t*4, 64+t*4}),
// fp32x2 packed FMA (32 FFMA2 per k per thread), double-buffered smem.
// ---------------------------------------------------------------------------
__device__ __forceinline__ void gemm128_tile(
    const float* __restrict__ X, const float* __restrict__ W,
    const float* __restrict__ bias, float* __restrict__ out,
    int m0, int n0, int K, int ldo)
{
    __shared__ float As[2][16][132];   // [buf][k][m]
    __shared__ float Bs[2][16][132];   // [buf][k][n]

    const int tid = threadIdx.x;
    const int tn = tid & 15, tm = tid >> 4;
    const int lr = tid >> 2;            // 0..63
    const int lk = (tid & 3) << 2;      // 0,4,8,12

    const float* Xp  = X + (size_t)(m0 + lr) * K + lk;
    const float* Xp2 = Xp + (size_t)64 * K;
    const float* Wp  = W + (size_t)(n0 + lr) * K + lk;
    const float* Wp2 = Wp + (size_t)64 * K;

    u64 acc[4][8];
    #pragma unroll
    for (int i = 0; i < 4; ++i)
        #pragma unroll
        for (int j = 0; j < 8; ++j) acc[i][j] = 0ull;

    // prologue: load k-slab 0 into smem buf 0
    float4 xa0 = *(const float4*)Xp;
    float4 xa1 = *(const float4*)Xp2;
    float4 wb0 = *(const float4*)Wp;
    float4 wb1 = *(const float4*)Wp2;
    #pragma unroll
    for (int j = 0; j < 4; ++j) {
        As[0][lk+j][lr]    = ((const float*)&xa0)[j];
        As[0][lk+j][lr+64] = ((const float*)&xa1)[j];
        Bs[0][lk+j][lr]    = ((const float*)&wb0)[j];
        Bs[0][lk+j][lr+64] = ((const float*)&wb1)[j];
    }
    __syncthreads();

    int buf = 0;
    for (int k0 = 16; k0 <= K; k0 += 16) {
        const bool more = (k0 < K);
        if (more) {
            xa0 = *(const float4*)(Xp  + k0);
            xa1 = *(const float4*)(Xp2 + k0);
            wb0 = *(const float4*)(Wp  + k0);
            wb1 = *(const float4*)(Wp2 + k0);
        }
        // compute on current buffer
        #pragma unroll
        for (int kk = 0; kk < 16; ++kk) {
            const float* as = &As[buf][kk][tm*4];
            const float* bs = &Bs[buf][kk][tn*4];
            ulonglong2 aA = *(const ulonglong2*)as;        // rows tm*4..+3
            ulonglong2 aB = *(const ulonglong2*)(as + 64); // rows 64+tm*4..+3
            float4 b0 = *(const float4*)bs;                // cols tn*4..+3
            float4 b1 = *(const float4*)(bs + 64);         // cols 64+tn*4..+3
            u64 aa[4] = { aA.x, aA.y, aB.x, aB.y };
            u64 bb[8];
            bb[0] = pk2(b0.x, b0.x); bb[1] = pk2(b0.y, b0.y);
            bb[2] = pk2(b0.z, b0.z); bb[3] = pk2(b0.w, b0.w);
            bb[4] = pk2(b1.x, b1.x); bb[5] = pk2(b1.y, b1.y);
            bb[6] = pk2(b1.z, b1.z); bb[7] = pk2(b1.w, b1.w);
            #pragma unroll
            for (int i = 0; i < 4; ++i)
                #pragma unroll
                for (int j = 0; j < 8; ++j)
                    ffma2(acc[i][j], aa[i], bb[j]);
        }
        if (more) {
            #pragma unroll
            for (int j = 0; j < 4; ++j) {
                As[buf^1][lk+j][lr]    = ((const float*)&xa0)[j];
                As[buf^1][lk+j][lr+64] = ((const float*)&xa1)[j];
                Bs[buf^1][lk+j][lr]    = ((const float*)&wb0)[j];
                Bs[buf^1][lk+j][lr+64] = ((const float*)&wb1)[j];
            }
            __syncthreads();
            buf ^= 1;
        }
    }

    // epilogue
    const float4 ba = *(const float4*)(bias + n0 + tn*4);
    const float4 bb4 = *(const float4*)(bias + n0 + 64 + tn*4);
    #pragma unroll
    for (int rp = 0; rp < 4; ++rp) {
        const int r = m0 + ((rp < 2) ? (tm*4 + 2*rp) : (64 + tm*4 + 2*(rp-2)));
        float lo[8], hi[8];
        #pragma unroll
        for (int j = 0; j < 8; ++j) upk2(acc[rp][j], lo[j], hi[j]);
        float4 s;
        s.x = lo[0]+ba.x; s.y = lo[1]+ba.y; s.z = lo[2]+ba.z; s.w = lo[3]+ba.w;
        *(float4*)(out + (size_t)r*ldo + n0 + tn*4) = s;
        s.x = lo[4]+bb4.x; s.y = lo[5]+bb4.y; s.z = lo[6]+bb4.z; s.w = lo[7]+bb4.w;
        *(float4*)(out + (size_t)r*ldo + n0 + 64 + tn*4) = s;
        s.x = hi[0]+ba.x; s.y = hi[1]+ba.y; s.z = hi[2]+ba.z; s.w = hi[3]+ba.w;
        *(float4*)(out + (size_t)(r+1)*ldo + n0 + tn*4) = s;
        s.x = hi[4]+bb4.x; s.y = hi[5]+bb4.y; s.z = hi[6]+bb4.z; s.w = hi[7]+bb4.w;
        *(float4*)(out + (size_t)(r+1)*ldo + n0 + 64 + tn*4) = s;
    }
}

// Fused QKV projection: grid.x in [0,10): 0..7 -> Q cols, 8 -> K, 9 -> V
__global__ __launch_bounds__(256, 2) void qkv_gemm_kernel(
    const float* __restrict__ x,
    const float* __restrict__ Wq, const float* __restrict__ bq,
    const float* __restrict__ Wk, const float* __restrict__ bk,
    const float* __restrict__ Wv, const float* __restrict__ bv)
{
    const int nb = blockIdx.x;
    const float* W; const float* bias; float* out; int n0; int ldo;
    if (nb < 8)       { W = Wq; bias = bq; out = g_q; n0 = nb*128; ldo = HQ*HD; }
    else if (nb == 8) { W = Wk; bias = bk; out = g_k; n0 = 0;      ldo = HKV*HD; }
    else              { W = Wv; bias = bv; out = g_v; n0 = 0;      ldo = HKV*HD; }
    gemm128_tile(x, W, bias, out, blockIdx.y*128, n0, CC, ldo);
}

__global__ __launch_bounds__(256, 2) void oproj_kernel(
    const float* __restrict__ Wo, const float* __restrict__ bo,
    float* __restrict__ out)
{
    gemm128_tile(g_y, Wo, bo, out, blockIdx.y*128, blockIdx.x*128, CC, CC);
}

// ---------------------------------------------------------------------------
// In-place RoPE over buf laid out [b][t][H][HD].
// ---------------------------------------------------------------------------
__global__ void rope_kernel(float* __restrict__ buf,
                            const float* __restrict__ rc,
                            int H, float postscale, int npairs)
{
    int idx = blockIdx.x * blockDim.x + threadIdx.x;
    if (idx >= npairs) return;
    int pair = idx & 31;                  // HD/2 = 32 pairs
    int t = (idx / (32 * H)) % TT;
    float2 xv = *(float2*)(buf + 2 * (size_t)idx);
    float sn = rc[t * HD + 2 * pair];
    float cs = rc[t * HD + 2 * pair + 1];
    float2 ov;
    ov.x = (xv.x * cs - xv.y * sn) * postscale;
    ov.y = (xv.y * cs + xv.x * sn) * postscale;
    *(float2*)(buf + 2 * (size_t)idx) = ov;
}

// ---------------------------------------------------------------------------
// Flash attention v2. grid (T/64, HQ, B), 256 threads (8 warps), BK=64.
// Warp w owns q-rows 8w..8w+7. Lane l owns k-cols l and l+32 of the 64-tile.
// QsT[d][row], Ks[col][d], Vs[row][d], PsT[col][row] in dynamic smem.
// S and PV phases packed over q-row pairs via fp32x2.
// ---------------------------------------------------------------------------
#define FPAD 68
#define FLASH_SMEM (4*64*FPAD*4)

__global__ __launch_bounds__(256) void flash_kernel()
{
    extern __shared__ float fsm[];
    float* QsT = fsm;                 // [64][68]  QsT[d][row]
    float* Ksm = fsm + 64*FPAD;       // [64][68]  Ks[col][d]
    float* Vsm = fsm + 2*64*FPAD;     // [64][68]  Vs[row][d]
    float* PsT = fsm + 3*64*FPAD;     // [64][68]  PsT[col][row]

    const int qb = blockIdx.x, h = blockIdx.y, b = blockIdx.z;
    const int qs = qb * 64;
    const int hk = h / (HQ / HKV);
    const int tid = threadIdx.x, w = tid >> 5, l = tid & 31;

    // Load Q tile transposed: QsT[d][row]
    for (int it = tid; it < 64 * 16; it += 256) {
        int rr = it >> 4, c4 = (it & 15) * 4;
        float4 val = *(const float4*)(g_q +
            ((((size_t)b * TT + qs + rr) * HQ + h) * HD) + c4);
        QsT[(c4+0)*FPAD + rr] = val.x;
        QsT[(c4+1)*FPAD + rr] = val.y;
        QsT[(c4+2)*FPAD + rr] = val.z;
        QsT[(c4+3)*FPAD + rr] = val.w;
    }

    float m_[8], lsum[8];
    u64 O2[4][2];   // [rowpair][dhalf: d=l | d=l+32]
    #pragma unroll
    for (int i = 0; i < 8; ++i) { m_[i] = -1e30f; lsum[i] = 0.f; }
    #pragma unroll
    for (int i = 0; i < 4; ++i) { O2[i][0] = 0ull; O2[i][1] = 0ull; }

    for (int kt = 0; kt <= qb; ++kt) {
        __syncthreads();
        // Load K,V tiles (64 x 64 each)
        for (int it = tid; it < 64 * 16; it += 256) {
            int rr = it >> 4, c4 = (it & 15) * 4;
            size_t base = ((((size_t)b * TT + kt * 64 + rr) * HKV + hk) * HD) + c4;
            *(float4*)&Ksm[rr*FPAD + c4] = *(const float4*)(g_k + base);
            *(float4*)&Vsm[rr*FPAD + c4] = *(const float4*)(g_v + base);
        }
        __syncthreads();

        // ---- S = Q.K^T, row-pair packed ----
        u64 s2[4][2];
        #pragma unroll
        for (int i = 0; i < 4; ++i) { s2[i][0] = 0ull; s2[i][1] = 0ull; }
        #pragma unroll 4
        for (int d4 = 0; d4 < 16; ++d4) {
            float4 k0v = *(const float4*)&Ksm[l*FPAD + d4*4];
            float4 k1v = *(const float4*)&Ksm[(l+32)*FPAD + d4*4];
            #pragma unroll
            for (int dd = 0; dd < 4; ++dd) {
                const int d = d4*4 + dd;
                const float kd0 = ((const float*)&k0v)[dd];
                const float kd1 = ((const float*)&k1v)[dd];
                u64 kp0 = pk2(kd0, kd0);
                u64 kp1 = pk2(kd1, kd1);
                ulonglong2 qA = *(const ulonglong2*)&QsT[d*FPAD + 8*w];
                ulonglong2 qB = *(const ulonglong2*)&QsT[d*FPAD + 8*w + 4];
                ffma2(s2[0][0], qA.x, kp0); ffma2(s2[0][1], qA.x, kp1);
                ffma2(s2[1][0], qA.y, kp0); ffma2(s2[1][1], qA.y, kp1);
                ffma2(s2[2][0], qB.x, kp0); ffma2(s2[2][1], qB.x, kp1);
                ffma2(s2[3][0], qB.y, kp0); ffma2(s2[3][1], qB.y, kp1);
            }
        }

        // unpack scores: sA = col c0+l, sB = col c0+l+32
        float sA[8], sB[8];
        #pragma unroll
        for (int rp = 0; rp < 4; ++rp) {
            upk2(s2[rp][0], sA[2*rp], sA[2*rp+1]);
            upk2(s2[rp][1], sB[2*rp], sB[2*rp+1]);
        }

        // ---- online softmax ----
        const bool diag = (kt == qb);
        const int c0 = kt * 64;
        float corr[8];
        #pragma unroll
        for (int i = 0; i < 8; ++i) {
            const int grow = qs + 8*w + i;
            float sv0 = sA[i], sv1 = sB[i];
            if (diag) {
                if (c0 + l      > grow) sv0 = -1e30f;
                if (c0 + l + 32 > grow) sv1 = -1e30f;
            }
            float mx = fmaxf(sv0, sv1);
            #pragma unroll
            for (int off = 16; off; off >>= 1)
                mx = fmaxf(mx, __shfl_xor_sync(0xffffffffu, mx, off));
            const float newm = fmaxf(m_[i], mx);
            const float p0 = __expf(sv0 - newm);
            const float p1 = __expf(sv1 - newm);
            float rs = p0 + p1;
            #pragma unroll
            for (int off = 16; off; off >>= 1)
                rs += __shfl_xor_sync(0xffffffffu, rs, off);
            corr[i] = __expf(m_[i] - newm);
            lsum[i] = lsum[i] * corr[i] + rs;
            m_[i] = newm;
            PsT[l*FPAD + 8*w + i]      = p0;
            PsT[(l+32)*FPAD + 8*w + i] = p1;
        }
        #pragma unroll
        for (int rp = 0; rp < 4; ++rp) {
            u64 cp = pk2(corr[2*rp], corr[2*rp+1]);
            fmul2(O2[rp][0], cp);
            fmul2(O2[rp][1], cp);
        }
        __syncwarp();

        // ---- O += P.V, row-pair packed ----
        #pragma unroll 8
        for (int j = 0; j < 64; ++j) {
            ulonglong2 pA = *(const ulonglong2*)&PsT[j*FPAD + 8*w];
            ulonglong2 pB = *(const ulonglong2*)&PsT[j*FPAD + 8*w + 4];
            const float v0 = Vsm[j*FPAD + l];
            const float v1 = Vsm[j*FPAD + l + 32];
            u64 vp0 = pk2(v0, v0);
            u64 vp1 = pk2(v1, v1);
            ffma2(O2[0][0], pA.x, vp0); ffma2(O2[0][1], pA.x, vp1);
            ffma2(O2[1][0], pA.y, vp0); ffma2(O2[1][1], pA.y, vp1);
            ffma2(O2[2][0], pB.x, vp0); ffma2(O2[2][1], pB.x, vp1);
            ffma2(O2[3][0], pB.y, vp0); ffma2(O2[3][1], pB.y, vp1);
        }
    }

    // normalize + write y [b][t][h][d]
    #pragma unroll
    for (int rp = 0; rp < 4; ++rp) {
        float o0lo, o0hi, o1lo, o1hi;
        upk2(O2[rp][0], o0lo, o0hi);   // d = l,    rows 2rp / 2rp+1
        upk2(O2[rp][1], o1lo, o1hi);   // d = l+32
        const int r0 = qs + 8*w + 2*rp;
        const float inv0 = 1.f / lsum[2*rp];
        const float inv1 = 1.f / lsum[2*rp + 1];
        size_t base0 = (((size_t)b * TT + r0) * HQ + h) * HD;
        size_t base1 = (((size_t)b * TT + r0 + 1) * HQ + h) * HD;
        g_y[base0 + l]      = o0lo * inv0;
        g_y[base0 + l + 32] = o1lo * inv0;
        g_y[base1 + l]      = o0hi * inv1;
        g_y[base1 + l + 32] = o1hi * inv1;
    }
}

// ---------------------------------------------------------------------------
extern "C" void kernel_launch(void* const* d_in, const int* in_sizes, int n_in,
                              void* d_out, int out_size)
{
    const float* x  = (const float*)d_in[0];
    const float* rc = (const float*)d_in[1];
    const float* Wq = (const float*)d_in[2];
    const float* bq = (const float*)d_in[3];
    const float* Wk = (const float*)d_in[4];
    const float* bk = (const float*)d_in[5];
    const float* Wv = (const float*)d_in[6];
    const float* bv = (const float*)d_in[7];
    const float* Wo = (const float*)d_in[8];
    const float* bo = (const float*)d_in[9];
    float* out = (float*)d_out;

    float *qb, *kb;
    cudaGetSymbolAddress((void**)&qb, g_q);
    cudaGetSymbolAddress((void**)&kb, g_k);

    cudaFuncSetAttribute(flash_kernel,
                         cudaFuncAttributeMaxDynamicSharedMemorySize, FLASH_SMEM);

    // Fused QKV projection
    qkv_gemm_kernel<<<dim3(10, MROWS / 128), 256>>>(x, Wq, bq, Wk, bk, Wv, bv);

    // RoPE (+ fold scale^2 = 1/HD into q)
    {
        int nq = BB * TT * HQ * (HD / 2);
        int nk = BB * TT * HKV * (HD / 2);
        rope_kernel<<<(nq + 255) / 256, 256>>>(qb, rc, HQ, 1.0f / (float)HD, nq);
        rope_kernel<<<(nk + 255) / 256, 256>>>(kb, rc, HKV, 1.0f, nk);
    }

    // Causal flash attention
    flash_kernel<<<dim3(TT / 64, HQ, BB), 256, FLASH_SMEM>>>();

    // Output projection
    oproj_kernel<<<dim3(CC / 128, MROWS / 128), 256>>>(Wo, bo, out);
}